// round 4
// baseline (speedup 1.0000x reference)
#include <cuda_runtime.h>
#include <math.h>

// ---------------- problem constants ----------------
#define Nn    101376          // total nodes
#define Ee    202752          // total edges
#define Gg    528             // graphs
#define NPGc  192             // nodes per graph
#define KTOP  30              // sort-pool k
#define Dd    769             // concat channel dim
#define MAXDEG 32

// ---------------- scratch layout in one zero-init device global -------------
static const size_t OF_H   = 0;                                  // [N,256] gemm temp
static const size_t OF_X1  = OF_H   + (size_t)Nn*256;
static const size_t OF_X2  = OF_X1  + (size_t)Nn*256;
static const size_t OF_X3  = OF_X2  + (size_t)Nn*256;
static const size_t OF_X4  = OF_X3  + (size_t)Nn*256;            // [N]
static const size_t OF_H4  = OF_X4  + (size_t)Nn;                // [N]
static const size_t OF_DIS = OF_H4  + (size_t)Nn;                // [N]
static const size_t OF_XS  = OF_DIS + (size_t)Nn;                // [G*K, 769]
static const size_t OF_Y5  = OF_XS  + (size_t)Gg*KTOP*Dd;        // [G*30, 128]
static const size_t OF_Y2  = OF_Y5  + (size_t)Gg*30*128;         // [G,15,128]
static const size_t OF_W5T = OF_Y2  + (size_t)Gg*15*128;         // [769,128]
static const size_t OF_W6T = OF_W5T + (size_t)769*128;           // [640,256]
static const size_t OF_O6  = OF_W6T + (size_t)640*256;           // [48,30976]
static const size_t OF_EMT = OF_O6  + (size_t)48*30976;          // [30976,48]
static const size_t OF_HP  = OF_EMT + (size_t)48*30976;          // [48,256]
static const size_t OF_END = OF_HP  + (size_t)48*256;
__device__ float g_f[OF_END];

static const size_t OI_CNT = 0;                                  // [N]
static const size_t OI_ADJ = OI_CNT + (size_t)Nn;                // [N,32]
static const size_t OI_IDX = OI_ADJ + (size_t)Nn*MAXDEG;         // [G,30]
static const size_t OI_AOF = OI_IDX + (size_t)Gg*KTOP;           // [5808]
static const size_t OI_COF = OI_AOF + 5808;                      // [5808]
static const size_t OI_END = OI_COF + 5808;
__device__ int g_i[OI_END];

// ---------------- small utility kernels ----------------
__global__ void k_zero_cnt() {
    int i = blockIdx.x*blockDim.x + threadIdx.x;
    if (i < Nn) g_i[OI_CNT + i] = 0;
}
__global__ void k_zero_hp() {
    int i = blockIdx.x*blockDim.x + threadIdx.x;
    if (i < 48*256) g_f[OF_HP + i] = 0.f;
}

// build fixed-width adjacency (incoming edges per dst)
__global__ void k_build(const int* __restrict__ src, const int* __restrict__ dst) {
    int e = blockIdx.x*blockDim.x + threadIdx.x;
    if (e >= Ee) return;
    int d = dst[e];
    int p = atomicAdd(&g_i[OI_CNT + d], 1);
    if (p < MAXDEG) g_i[OI_ADJ + (size_t)d*MAXDEG + p] = src[e];
}

// deterministic order (sort adjacency) + dis = rsqrt(deg)
__global__ void k_dis() {
    int i = blockIdx.x*blockDim.x + threadIdx.x;
    if (i >= Nn) return;
    int n = g_i[OI_CNT + i]; if (n > MAXDEG) n = MAXDEG;
    g_i[OI_CNT + i] = n;
    int* a = &g_i[OI_ADJ + (size_t)i*MAXDEG];
    for (int p = 1; p < n; p++) {
        int key = a[p]; int q = p-1;
        while (q >= 0 && a[q] > key) { a[q+1] = a[q]; q--; }
        a[q+1] = key;
    }
    g_f[OF_DIS + i] = rsqrtf(1.0f + (float)n);
}

// ---------------- generic tiled SGEMM  C[M,N] = A[M,K] * B[K,N] ----------------
// A = Aext ? Aext : g_f+Aoff. Row base = useAOF ? g_i[OI_AOF+row] : row*lda.
// B = Bext ? Bext : g_f+Boff. C = g_f + Coff, out index =
// (useCOF ? g_i[OI_COF+row] : row*N) + n*cstride. Optional ext bias + relu.
__global__ __launch_bounds__(256)
void sgemm(const float* __restrict__ Aext, size_t Aoff, int lda, int useAOF,
           const float* __restrict__ Bext, size_t Boff,
           size_t Coff, int useCOF, int cstride,
           int M, int N, int K,
           const float* __restrict__ bias, int act) {
    const float* A = Aext ? Aext : (const float*)(g_f + Aoff);
    const float* B = Bext ? Bext : (const float*)(g_f + Boff);
    float* C = g_f + Coff;

    __shared__ __align__(16) float As[16][132];
    __shared__ __align__(16) float Bs[16][68];
    const int tid = threadIdx.x;
    const int bm = blockIdx.y * 128;
    const int bn = blockIdx.x * 64;
    const int tm0 = (tid >> 4) * 8;   // 0..120
    const int tn0 = (tid & 15) * 4;   // 0..60
    float acc[8][4];
    #pragma unroll
    for (int i = 0; i < 8; i++)
        #pragma unroll
        for (int j = 0; j < 4; j++) acc[i][j] = 0.f;

    for (int k0 = 0; k0 < K; k0 += 16) {
        #pragma unroll
        for (int l = 0; l < 8; l++) {           // A tile: 128x16
            int lin = l*256 + tid;
            int r = lin >> 4, c = lin & 15;
            int row = bm + r, k = k0 + c;
            float v = 0.f;
            if (row < M && k < K) {
                long base = useAOF ? (long)g_i[OI_AOF + row] : (long)row * lda;
                v = A[base + k];
            }
            As[c][r] = v;
        }
        #pragma unroll
        for (int l = 0; l < 4; l++) {           // B tile: 16x64
            int lin = l*256 + tid;
            int kr = lin >> 6, c = lin & 63;
            int k = k0 + kr;
            Bs[kr][c] = (k < K) ? B[(long)k*N + bn + c] : 0.f;
        }
        __syncthreads();
        #pragma unroll
        for (int kk = 0; kk < 16; kk++) {
            float4 a0 = *(const float4*)&As[kk][tm0];
            float4 a1 = *(const float4*)&As[kk][tm0+4];
            float4 b0 = *(const float4*)&Bs[kk][tn0];
            float a[8] = {a0.x,a0.y,a0.z,a0.w,a1.x,a1.y,a1.z,a1.w};
            float b[4] = {b0.x,b0.y,b0.z,b0.w};
            #pragma unroll
            for (int i = 0; i < 8; i++)
                #pragma unroll
                for (int j = 0; j < 4; j++) acc[i][j] += a[i]*b[j];
        }
        __syncthreads();
    }

    #pragma unroll
    for (int i = 0; i < 8; i++) {
        int row = bm + tm0 + i;
        if (row >= M) continue;
        long cbase = useCOF ? (long)g_i[OI_COF + row] : (long)row * N;
        #pragma unroll
        for (int j = 0; j < 4; j++) {
            int n = bn + tn0 + j;
            float v = acc[i][j];
            if (bias) v += bias[n];
            if (act == 1) v = fmaxf(v, 0.f);
            C[cbase + (long)n * cstride] = v;
        }
    }
}

// ---------------- GCN aggregation (C=256): block per node ----------------
// h = g_f+OF_H, out = g_f+outOff, bias external
__global__ void k_agg(size_t outOff, const float* __restrict__ bias) {
    const float* h = g_f + OF_H;
    int i = blockIdx.x;
    int c = threadIdx.x;
    float di = g_f[OF_DIS + i];
    float v = h[(size_t)i*256 + c] * di * di;
    int n = g_i[OI_CNT + i];
    const int* a = &g_i[OI_ADJ + (size_t)i*MAXDEG];
    for (int e = 0; e < n; e++) {
        int s = a[e];
        v += h[(size_t)s*256 + c] * (g_f[OF_DIS + s] * di);
    }
    g_f[outOff + (size_t)i*256 + c] = tanhf(v + bias[c]);
}

// layer-4 projection: h4[n] = dot(x3[n,:256], W4)  (warp per node)
__global__ void k_l4(const float* __restrict__ W4) {
    int warp = (blockIdx.x*blockDim.x + threadIdx.x) >> 5;
    int lane = threadIdx.x & 31;
    if (warp >= Nn) return;
    const float* row = g_f + OF_X3 + (size_t)warp*256;
    float s = 0.f;
    #pragma unroll
    for (int c = lane; c < 256; c += 32) s += row[c] * W4[c];
    #pragma unroll
    for (int o = 16; o; o >>= 1) s += __shfl_xor_sync(0xffffffffu, s, o);
    if (lane == 0) g_f[OF_H4 + warp] = s;
}

// aggregation C=1 + tanh -> x4
__global__ void k_agg1(const float* __restrict__ b4) {
    int i = blockIdx.x*blockDim.x + threadIdx.x;
    if (i >= Nn) return;
    const float* h = g_f + OF_H4;
    float di = g_f[OF_DIS + i];
    float v = h[i] * di * di;
    int n = g_i[OI_CNT + i];
    const int* a = &g_i[OI_ADJ + (size_t)i*MAXDEG];
    for (int e = 0; e < n; e++) { int s = a[e]; v += h[s] * g_f[OF_DIS + s] * di; }
    g_f[OF_X4 + i] = tanhf(v + b4[0]);
}

// per-graph top-K by last channel: bitonic sort of 256 (value desc, idx asc)
__global__ void k_topk() {
    __shared__ float key[256];
    __shared__ int   val[256];
    int g = blockIdx.x, t = threadIdx.x;
    key[t] = (t < NPGc) ? g_f[OF_X4 + (size_t)g*NPGc + t] : -2.0f;  // tanh in (-1,1)
    val[t] = t;
    __syncthreads();
    for (int k = 2; k <= 256; k <<= 1) {
        for (int j = k >> 1; j > 0; j >>= 1) {
            int ixj = t ^ j;
            if (ixj > t) {
                float ka = key[t], kb = key[ixj];
                int   va = val[t], vb = val[ixj];
                bool before = (ka > kb) || (ka == kb && va < vb);
                bool dir = ((t & k) == 0);
                if (before != dir) { key[t]=kb; key[ixj]=ka; val[t]=vb; val[ixj]=va; }
            }
            __syncthreads();
        }
    }
    if (t < KTOP) g_i[OI_IDX + g*KTOP + t] = val[t];
}

// gather selected rows into xs [G*K, 769]
__global__ void k_gather() {
    int m = blockIdx.x;                 // 0..15839
    int g = m / KTOP;
    int node = g*NPGc + g_i[OI_IDX + m];
    int c = threadIdx.x;
    float* row = g_f + OF_XS + (size_t)m * Dd;
    row[c]       = g_f[OF_X1 + (size_t)node*256 + c];
    row[256 + c] = g_f[OF_X2 + (size_t)node*256 + c];
    row[512 + c] = g_f[OF_X3 + (size_t)node*256 + c];
    if (c == 0) row[768] = g_f[OF_X4 + node];
}

// weight re-layouts
__global__ void k_w5t(const float* __restrict__ w5) {
    int i = blockIdx.x*blockDim.x + threadIdx.x;
    if (i >= 769*128) return;
    int d = i >> 7, oc = i & 127;
    g_f[OF_W5T + i] = w5[oc*Dd + d];
}
__global__ void k_w6t(const float* __restrict__ w6) {
    int i = blockIdx.x*blockDim.x + threadIdx.x;
    if (i >= 640*256) return;
    int k = i >> 8, o = i & 255;
    int ic = k & 127, j = k >> 7;
    g_f[OF_W6T + i] = w6[o*640 + ic*5 + j];
}
__global__ void k_off6() {
    int m = blockIdx.x*blockDim.x + threadIdx.x;
    if (m >= 5808) return;
    int g = m / 11, t = m - g*11;
    g_i[OI_AOF + m] = g*15*128 + t*128;   // A row start inside y2 buffer
    g_i[OI_COF + m] = g*2816 + t;         // out6 base; +oc2*11
}

// maxpool(2,2) over conv5 output -> y2 [G,15,128]
__global__ void k_pool() {
    int i = blockIdx.x*blockDim.x + threadIdx.x;
    if (i >= Gg*15*128) return;
    int oc = i & 127;
    int r = i >> 7;
    int p = r % 15, g = r / 15;
    float a = g_f[OF_Y5 + (size_t)(g*30 + 2*p)*128 + oc];
    float b = g_f[OF_Y5 + (size_t)(g*30 + 2*p + 1)*128 + oc];
    g_f[OF_Y2 + i] = fmaxf(a, b);
}

// transpose emb (=out6) [48,30976] -> embT [30976,48]
__global__ void k_embT() {
    int k = blockIdx.x*blockDim.x + threadIdx.x;
    if (k >= 30976) return;
    #pragma unroll 4
    for (int b = 0; b < 48; b++)
        g_f[OF_EMT + (size_t)k*48 + b] = g_f[OF_O6 + (size_t)b*30976 + k];
}

// dense1: hpre[b,o] += sum_k emb[b,k]*Wc1[k,o]  (split-K, atomic reduce)
__global__ __launch_bounds__(256)
void k_dense1(const float* __restrict__ Wc1) {
    const int KC = 242;                 // 128 blocks * 242 = 30976
    int o = threadIdx.x;
    int k0 = blockIdx.x * KC;
    float acc[48];
    #pragma unroll
    for (int b = 0; b < 48; b++) acc[b] = 0.f;
    __shared__ __align__(16) float esm[22*48];
    for (int s = 0; s < KC; s += 22) {
        for (int l = threadIdx.x; l < 22*48; l += 256)
            esm[l] = g_f[OF_EMT + (size_t)(k0+s)*48 + l];
        __syncthreads();
        #pragma unroll 2
        for (int kk = 0; kk < 22; kk++) {
            float w = Wc1[(size_t)(k0+s+kk)*256 + o];
            const float4* e4 = (const float4*)&esm[kk*48];
            #pragma unroll
            for (int bb = 0; bb < 12; bb++) {
                float4 e = e4[bb];
                acc[bb*4+0] += e.x*w; acc[bb*4+1] += e.y*w;
                acc[bb*4+2] += e.z*w; acc[bb*4+3] += e.w*w;
            }
        }
        __syncthreads();
    }
    #pragma unroll
    for (int b = 0; b < 48; b++) atomicAdd(&g_f[OF_HP + b*256 + o], acc[b]);
}

// dense2: relu(hpre+bc1) @ Wc2 + bc2 -> logits [48,10]
__global__ void k_dense2(const float* __restrict__ bc1, const float* __restrict__ Wc2,
                         const float* __restrict__ bc2, float* __restrict__ out) {
    __shared__ float hs[48*256];
    int tid = threadIdx.x;
    for (int l = tid; l < 48*256; l += blockDim.x)
        hs[l] = fmaxf(g_f[OF_HP + l] + bc1[l & 255], 0.f);
    __syncthreads();
    if (tid < 480) {
        int b = tid / 10, o = tid - b*10;
        float s = bc2[o];
        for (int j = 0; j < 256; j++) s += hs[b*256 + j] * Wc2[j*10 + o];
        out[tid] = s;
    }
}

// ---------------- launch (kernel launches ONLY — no other CUDA APIs) --------
extern "C" void kernel_launch(void* const* d_in, const int* in_sizes, int n_in,
                              void* d_out, int out_size) {
    const float* x    = (const float*)d_in[0];
    const int*   src  = (const int*)  d_in[1];
    const int*   dstp = (const int*)  d_in[2];
    const float* W1   = (const float*)d_in[3];
    const float* b1   = (const float*)d_in[4];
    const float* W2   = (const float*)d_in[5];
    const float* b2   = (const float*)d_in[6];
    const float* W3   = (const float*)d_in[7];
    const float* b3   = (const float*)d_in[8];
    const float* W4   = (const float*)d_in[9];
    const float* b4   = (const float*)d_in[10];
    const float* w5   = (const float*)d_in[11];
    const float* bc5  = (const float*)d_in[12];
    const float* w6   = (const float*)d_in[13];
    const float* bc6  = (const float*)d_in[14];
    const float* Wc1  = (const float*)d_in[15];
    const float* bc1  = (const float*)d_in[16];
    const float* Wc2  = (const float*)d_in[17];
    const float* bc2  = (const float*)d_in[18];
    float* out = (float*)d_out;

    // graph structure
    k_zero_cnt<<<(Nn+255)/256, 256>>>();
    k_build<<<(Ee+255)/256, 256>>>(src, dstp);
    k_dis<<<(Nn+255)/256, 256>>>();

    // weight re-layouts + offset tables (cheap, every launch)
    k_w5t<<<(769*128+255)/256, 256>>>(w5);
    k_w6t<<<(640*256+255)/256, 256>>>(w6);
    k_off6<<<(5808+255)/256, 256>>>();

    // GCN layers: XW (into H) then normalize+aggregate+tanh
    sgemm<<<dim3(4,792), 256>>>(x, 0, 64, 0,  W1, 0, OF_H, 0, 1, Nn, 256, 64,  nullptr, 0);
    k_agg<<<Nn, 256>>>(OF_X1, b1);
    sgemm<<<dim3(4,792), 256>>>(nullptr, OF_X1, 256, 0, W2, 0, OF_H, 0, 1, Nn, 256, 256, nullptr, 0);
    k_agg<<<Nn, 256>>>(OF_X2, b2);
    sgemm<<<dim3(4,792), 256>>>(nullptr, OF_X2, 256, 0, W3, 0, OF_H, 0, 1, Nn, 256, 256, nullptr, 0);
    k_agg<<<Nn, 256>>>(OF_X3, b3);
    k_l4<<<(Nn*32+255)/256, 256>>>(W4);
    k_agg1<<<(Nn+255)/256, 256>>>(b4);

    // sort-pool + gather
    k_topk<<<Gg, 256>>>();
    k_gather<<<Gg*KTOP, 256>>>();

    // conv5 (stride=kernel=769) as GEMM [15840,769]x[769,128] + bias + relu
    sgemm<<<dim3(2,124), 256>>>(nullptr, OF_XS, Dd, 0, nullptr, OF_W5T, OF_Y5, 0, 1,
                                Gg*KTOP, 128, Dd, bc5, 1);
    k_pool<<<(Gg*15*128+255)/256, 256>>>();

    // conv6 as GEMM with row-offset indirection [5808,640]x[640,256], permuted store
    sgemm<<<dim3(4,46), 256>>>(nullptr, OF_Y2, 0, 1, nullptr, OF_W6T, OF_O6, 1, 11,
                               5808, 256, 640, bc6, 1);

    // dense head
    k_embT<<<(30976+255)/256, 256>>>();
    k_zero_hp<<<(48*256+255)/256, 256>>>();
    k_dense1<<<128, 256>>>(Wc1);
    k_dense2<<<1, 512>>>(bc1, Wc2, bc2, out);
}

// round 7
// speedup vs baseline: 1.1546x; 1.1546x over previous
#include <cuda_runtime.h>
#include <math.h>

// ---------------- problem constants ----------------
#define Nn    101376          // total nodes
#define Ee    202752          // total edges
#define Gg    528             // graphs
#define NPGc  192             // nodes per graph
#define KTOP  30              // sort-pool k
#define Dd    769             // concat channel dim
#define MAXDEG 32

// ---------------- scratch layout in one zero-init device global -------------
static const size_t OF_H   = 0;                                  // [N,256] gemm temp
static const size_t OF_X1  = OF_H   + (size_t)Nn*256;
static const size_t OF_X2  = OF_X1  + (size_t)Nn*256;
static const size_t OF_X3  = OF_X2  + (size_t)Nn*256;
static const size_t OF_X4  = OF_X3  + (size_t)Nn*256;            // [N]
static const size_t OF_H4  = OF_X4  + (size_t)Nn;                // [N]
static const size_t OF_DIS = OF_H4  + (size_t)Nn;                // [N]
static const size_t OF_XS  = OF_DIS + (size_t)Nn;                // [G*K, 769]
static const size_t OF_Y5  = OF_XS  + (size_t)Gg*KTOP*Dd;        // [G*30, 128]
static const size_t OF_Y2  = OF_Y5  + (size_t)Gg*30*128;         // [G,15,128]
static const size_t OF_W5T = OF_Y2  + (size_t)Gg*15*128;         // [769,128]
static const size_t OF_W6T = OF_W5T + (size_t)769*128;           // [640,256]
static const size_t OF_O6  = OF_W6T + (size_t)640*256;           // [48,30976]
static const size_t OF_EMT = OF_O6  + (size_t)48*30976;          // [30976,48]
static const size_t OF_HP  = OF_EMT + (size_t)48*30976;          // [48,256]
static const size_t OF_END = OF_HP  + (size_t)48*256;
__device__ float g_f[OF_END];

static const size_t OI_CNT = 0;                                  // [N]
static const size_t OI_ADJ = OI_CNT + (size_t)Nn;                // [N,32]
static const size_t OI_IDX = OI_ADJ + (size_t)Nn*MAXDEG;         // [G,30]
static const size_t OI_AOF = OI_IDX + (size_t)Gg*KTOP;           // [5808]
static const size_t OI_COF = OI_AOF + 5808;                      // [5808]
static const size_t OI_END = OI_COF + 5808;
__device__ int g_i[OI_END];

// ---------------- f32x2 packed helpers ----------------
typedef unsigned long long u64;
__device__ __forceinline__ u64 ffma2(u64 a, u64 b, u64 c) {
    u64 d;
    asm("fma.rn.f32x2 %0, %1, %2, %3;" : "=l"(d) : "l"(a), "l"(b), "l"(c));
    return d;
}
__device__ __forceinline__ u64 pack2(float lo, float hi) {
    u64 d;
    asm("mov.b64 %0, {%1, %2};" : "=l"(d) : "f"(lo), "f"(hi));
    return d;
}
__device__ __forceinline__ void unpack2(u64 v, float& lo, float& hi) {
    asm("mov.b64 {%0, %1}, %2;" : "=f"(lo), "=f"(hi) : "l"(v));
}

// ---------------- small utility kernels ----------------
__global__ void k_zero_cnt() {
    int i = blockIdx.x*blockDim.x + threadIdx.x;
    if (i < Nn) g_i[OI_CNT + i] = 0;
}
__global__ void k_zero_hp() {
    int i = blockIdx.x*blockDim.x + threadIdx.x;
    if (i < 48*256) g_f[OF_HP + i] = 0.f;
}

// build fixed-width adjacency (incoming edges per dst)
__global__ void k_build(const int* __restrict__ src, const int* __restrict__ dst) {
    int e = blockIdx.x*blockDim.x + threadIdx.x;
    if (e >= Ee) return;
    int d = dst[e];
    int p = atomicAdd(&g_i[OI_CNT + d], 1);
    if (p < MAXDEG) g_i[OI_ADJ + (size_t)d*MAXDEG + p] = src[e];
}

// deterministic order (sort adjacency) + dis = rsqrt(deg)
__global__ void k_dis() {
    int i = blockIdx.x*blockDim.x + threadIdx.x;
    if (i >= Nn) return;
    int n = g_i[OI_CNT + i]; if (n > MAXDEG) n = MAXDEG;
    g_i[OI_CNT + i] = n;
    int* a = &g_i[OI_ADJ + (size_t)i*MAXDEG];
    for (int p = 1; p < n; p++) {
        int key = a[p]; int q = p-1;
        while (q >= 0 && a[q] > key) { a[q+1] = a[q]; q--; }
        a[q+1] = key;
    }
    g_f[OF_DIS + i] = rsqrtf(1.0f + (float)n);
}

// ---------------- 128x128-tile f32x2 SGEMM  C[M,N] = A[M,K] * B[K,N] ----------
// A = Aext ? Aext : g_f+Aoff. Row base = useAOF ? g_i[OI_AOF+row] : row*lda.
// vecA=1 requires: K%16==0 and all row bases 4-float aligned.
// B = Bext ? Bext : g_f+Boff (N%4==0; tiles fully covered by grid.x*128<=N).
// C = g_f + Coff, out index = (useCOF ? g_i[OI_COF+row] : row*N) + n*cstride.
__global__ __launch_bounds__(256)
void sgemm2(const float* __restrict__ Aext, size_t Aoff, int lda, int useAOF, int vecA,
            const float* __restrict__ Bext, size_t Boff,
            size_t Coff, int useCOF, int cstride,
            int M, int N, int K,
            const float* __restrict__ bias, int act) {
    const float* A = Aext ? Aext : (const float*)(g_f + Aoff);
    const float* B = Bext ? Bext : (const float*)(g_f + Boff);
    float* C = g_f + Coff;

    __shared__ __align__(16) float As[16][132];   // [k][m]
    __shared__ __align__(16) float Bs[16][132];   // [k][n]
    const int tid = threadIdx.x;
    const int bm = blockIdx.y * 128;
    const int bn = blockIdx.x * 128;
    const int ty = tid >> 4;          // 0..15 -> rows ty*8..ty*8+7
    const int tx = tid & 15;          // 0..15 -> cols tx*4..+3 and 64+tx*4..+3

    u64 acc[4][8];
    #pragma unroll
    for (int i = 0; i < 4; i++)
        #pragma unroll
        for (int j = 0; j < 8; j++) acc[i][j] = 0ull;

    for (int k0 = 0; k0 < K; k0 += 16) {
        // ---- A tile 128x16 into As[k][m] ----
        if (vecA) {
            #pragma unroll
            for (int l = 0; l < 2; l++) {
                int idx = l*256 + tid;            // 0..511 float4s
                int r = idx >> 2, c4 = idx & 3;
                int row = bm + r;
                float4 v = make_float4(0.f,0.f,0.f,0.f);
                if (row < M) {
                    long base = useAOF ? (long)g_i[OI_AOF + row] : (long)row * lda;
                    v = *(const float4*)&A[base + k0 + c4*4];
                }
                As[c4*4+0][r] = v.x; As[c4*4+1][r] = v.y;
                As[c4*4+2][r] = v.z; As[c4*4+3][r] = v.w;
            }
        } else {
            #pragma unroll
            for (int l = 0; l < 8; l++) {
                int lin = l*256 + tid;
                int r = lin >> 4, c = lin & 15;
                int row = bm + r, k = k0 + c;
                float v = 0.f;
                if (row < M && k < K) {
                    long base = useAOF ? (long)g_i[OI_AOF + row] : (long)row * lda;
                    v = A[base + k];
                }
                As[c][r] = v;
            }
        }
        // ---- B tile 16x128 into Bs[k][n] (always vector) ----
        #pragma unroll
        for (int l = 0; l < 2; l++) {
            int idx = l*256 + tid;                // 0..511 float4s
            int kr = idx >> 5, c4 = idx & 31;
            int k = k0 + kr;
            float4 v = make_float4(0.f,0.f,0.f,0.f);
            if (k < K) v = *(const float4*)&B[(long)k*N + bn + c4*4];
            *(float4*)&Bs[kr][c4*4] = v;
        }
        __syncthreads();

        #pragma unroll
        for (int kk = 0; kk < 16; kk++) {
            // 8 rows as 4 packed pairs (free reinterpret of aligned float4s)
            const u64* a2a = (const u64*)&As[kk][ty*8];      // pairs (r0,r1),(r2,r3)
            const u64* a2b = (const u64*)&As[kk][ty*8+4];    // pairs (r4,r5),(r6,r7)
            u64 a2[4] = { a2a[0], a2a[1], a2b[0], a2b[1] };
            float4 b0 = *(const float4*)&Bs[kk][tx*4];
            float4 b1 = *(const float4*)&Bs[kk][64 + tx*4];
            u64 bd[8];
            bd[0] = pack2(b0.x, b0.x); bd[1] = pack2(b0.y, b0.y);
            bd[2] = pack2(b0.z, b0.z); bd[3] = pack2(b0.w, b0.w);
            bd[4] = pack2(b1.x, b1.x); bd[5] = pack2(b1.y, b1.y);
            bd[6] = pack2(b1.z, b1.z); bd[7] = pack2(b1.w, b1.w);
            #pragma unroll
            for (int ri = 0; ri < 4; ri++)
                #pragma unroll
                for (int j = 0; j < 8; j++)
                    acc[ri][j] = ffma2(a2[ri], bd[j], acc[ri][j]);
        }
        __syncthreads();
    }

    // ---- epilogue ----
    #pragma unroll
    for (int ri = 0; ri < 4; ri++) {
        #pragma unroll
        for (int s = 0; s < 2; s++) {
            int row = bm + ty*8 + 2*ri + s;
            if (row >= M) continue;
            long cbase = useCOF ? (long)g_i[OI_COF + row] : (long)row * N;
            #pragma unroll
            for (int j = 0; j < 8; j++) {
                int col = bn + ((j < 4) ? (tx*4 + j) : (64 + tx*4 + (j-4)));
                float lo, hi; unpack2(acc[ri][j], lo, hi);
                float v = s ? hi : lo;
                if (bias) v += bias[col];
                if (act == 1) v = fmaxf(v, 0.f);
                C[cbase + (long)col * cstride] = v;
            }
        }
    }
}

// ---------------- GCN aggregation (C=256): block per node ----------------
__global__ void k_agg(size_t outOff, const float* __restrict__ bias) {
    const float* h = g_f + OF_H;
    int i = blockIdx.x;
    int c = threadIdx.x;
    float di = g_f[OF_DIS + i];
    float v = h[(size_t)i*256 + c] * di * di;
    int n = g_i[OI_CNT + i];
    const int* a = &g_i[OI_ADJ + (size_t)i*MAXDEG];
    for (int e = 0; e < n; e++) {
        int s = a[e];
        v += h[(size_t)s*256 + c] * (g_f[OF_DIS + s] * di);
    }
    g_f[outOff + (size_t)i*256 + c] = tanhf(v + bias[c]);
}

// layer-4 projection: h4[n] = dot(x3[n,:256], W4)  (warp per node)
__global__ void k_l4(const float* __restrict__ W4) {
    int warp = (blockIdx.x*blockDim.x + threadIdx.x) >> 5;
    int lane = threadIdx.x & 31;
    if (warp >= Nn) return;
    const float* row = g_f + OF_X3 + (size_t)warp*256;
    float s = 0.f;
    #pragma unroll
    for (int c = lane; c < 256; c += 32) s += row[c] * W4[c];
    #pragma unroll
    for (int o = 16; o; o >>= 1) s += __shfl_xor_sync(0xffffffffu, s, o);
    if (lane == 0) g_f[OF_H4 + warp] = s;
}

// aggregation C=1 + tanh -> x4
__global__ void k_agg1(const float* __restrict__ b4) {
    int i = blockIdx.x*blockDim.x + threadIdx.x;
    if (i >= Nn) return;
    const float* h = g_f + OF_H4;
    float di = g_f[OF_DIS + i];
    float v = h[i] * di * di;
    int n = g_i[OI_CNT + i];
    const int* a = &g_i[OI_ADJ + (size_t)i*MAXDEG];
    for (int e = 0; e < n; e++) { int s = a[e]; v += h[s] * g_f[OF_DIS + s] * di; }
    g_f[OF_X4 + i] = tanhf(v + b4[0]);
}

// per-graph top-K by last channel: bitonic sort of 256 (value desc, idx asc)
__global__ void k_topk() {
    __shared__ float key[256];
    __shared__ int   val[256];
    int g = blockIdx.x, t = threadIdx.x;
    key[t] = (t < NPGc) ? g_f[OF_X4 + (size_t)g*NPGc + t] : -2.0f;  // tanh in (-1,1)
    val[t] = t;
    __syncthreads();
    for (int k = 2; k <= 256; k <<= 1) {
        for (int j = k >> 1; j > 0; j >>= 1) {
            int ixj = t ^ j;
            if (ixj > t) {
                float ka = key[t], kb = key[ixj];
                int   va = val[t], vb = val[ixj];
                bool before = (ka > kb) || (ka == kb && va < vb);
                bool dir = ((t & k) == 0);
                if (before != dir) { key[t]=kb; key[ixj]=ka; val[t]=vb; val[ixj]=va; }
            }
            __syncthreads();
        }
    }
    if (t < KTOP) g_i[OI_IDX + g*KTOP + t] = val[t];
}

// gather selected rows into xs [G*K, 769]
__global__ void k_gather() {
    int m = blockIdx.x;                 // 0..15839
    int g = m / KTOP;
    int node = g*NPGc + g_i[OI_IDX + m];
    int c = threadIdx.x;
    float* row = g_f + OF_XS + (size_t)m * Dd;
    row[c]       = g_f[OF_X1 + (size_t)node*256 + c];
    row[256 + c] = g_f[OF_X2 + (size_t)node*256 + c];
    row[512 + c] = g_f[OF_X3 + (size_t)node*256 + c];
    if (c == 0) row[768] = g_f[OF_X4 + node];
}

// weight re-layouts
__global__ void k_w5t(const float* __restrict__ w5) {
    int i = blockIdx.x*blockDim.x + threadIdx.x;
    if (i >= 769*128) return;
    int d = i >> 7, oc = i & 127;
    g_f[OF_W5T + i] = w5[oc*Dd + d];
}
__global__ void k_w6t(const float* __restrict__ w6) {
    int i = blockIdx.x*blockDim.x + threadIdx.x;
    if (i >= 640*256) return;
    int k = i >> 8, o = i & 255;
    int ic = k & 127, j = k >> 7;
    g_f[OF_W6T + i] = w6[o*640 + ic*5 + j];
}
__global__ void k_off6() {
    int m = blockIdx.x*blockDim.x + threadIdx.x;
    if (m >= 5808) return;
    int g = m / 11, t = m - g*11;
    g_i[OI_AOF + m] = g*15*128 + t*128;   // A row start inside y2 buffer
    g_i[OI_COF + m] = g*2816 + t;         // out6 base; +oc2*11
}

// maxpool(2,2) over conv5 output -> y2 [G,15,128]
__global__ void k_pool() {
    int i = blockIdx.x*blockDim.x + threadIdx.x;
    if (i >= Gg*15*128) return;
    int oc = i & 127;
    int r = i >> 7;
    int p = r % 15, g = r / 15;
    float a = g_f[OF_Y5 + (size_t)(g*30 + 2*p)*128 + oc];
    float b = g_f[OF_Y5 + (size_t)(g*30 + 2*p + 1)*128 + oc];
    g_f[OF_Y2 + i] = fmaxf(a, b);
}

// transpose emb (=out6) [48,30976] -> embT [30976,48]
__global__ void k_embT() {
    int k = blockIdx.x*blockDim.x + threadIdx.x;
    if (k >= 30976) return;
    #pragma unroll 4
    for (int b = 0; b < 48; b++)
        g_f[OF_EMT + (size_t)k*48 + b] = g_f[OF_O6 + (size_t)b*30976 + k];
}

// dense1: hpre[b,o] += sum_k emb[b,k]*Wc1[k,o]  (split-K, atomic reduce)
__global__ __launch_bounds__(256)
void k_dense1(const float* __restrict__ Wc1) {
    const int KC = 242;                 // 128 blocks * 242 = 30976
    int o = threadIdx.x;
    int k0 = blockIdx.x * KC;
    float acc[48];
    #pragma unroll
    for (int b = 0; b < 48; b++) acc[b] = 0.f;
    __shared__ __align__(16) float esm[22*48];
    for (int s = 0; s < KC; s += 22) {
        for (int l = threadIdx.x; l < 22*48; l += 256)
            esm[l] = g_f[OF_EMT + (size_t)(k0+s)*48 + l];
        __syncthreads();
        #pragma unroll 2
        for (int kk = 0; kk < 22; kk++) {
            float w = Wc1[(size_t)(k0+s+kk)*256 + o];
            const float4* e4 = (const float4*)&esm[kk*48];
            #pragma unroll
            for (int bb = 0; bb < 12; bb++) {
                float4 e = e4[bb];
                acc[bb*4+0] += e.x*w; acc[bb*4+1] += e.y*w;
                acc[bb*4+2] += e.z*w; acc[bb*4+3] += e.w*w;
            }
        }
        __syncthreads();
    }
    #pragma unroll
    for (int b = 0; b < 48; b++) atomicAdd(&g_f[OF_HP + b*256 + o], acc[b]);
}

// dense2: relu(hpre+bc1) @ Wc2 + bc2 -> logits [48,10]
__global__ void k_dense2(const float* __restrict__ bc1, const float* __restrict__ Wc2,
                         const float* __restrict__ bc2, float* __restrict__ out) {
    __shared__ float hs[48*256];
    int tid = threadIdx.x;
    for (int l = tid; l < 48*256; l += blockDim.x)
        hs[l] = fmaxf(g_f[OF_HP + l] + bc1[l & 255], 0.f);
    __syncthreads();
    if (tid < 480) {
        int b = tid / 10, o = tid - b*10;
        float s = bc2[o];
        for (int j = 0; j < 256; j++) s += hs[b*256 + j] * Wc2[j*10 + o];
        out[tid] = s;
    }
}

// ---------------- launch (kernel launches ONLY — no other CUDA APIs) --------
extern "C" void kernel_launch(void* const* d_in, const int* in_sizes, int n_in,
                              void* d_out, int out_size) {
    const float* x    = (const float*)d_in[0];
    const int*   src  = (const int*)  d_in[1];
    const int*   dstp = (const int*)  d_in[2];
    const float* W1   = (const float*)d_in[3];
    const float* b1   = (const float*)d_in[4];
    const float* W2   = (const float*)d_in[5];
    const float* b2   = (const float*)d_in[6];
    const float* W3   = (const float*)d_in[7];
    const float* b3   = (const float*)d_in[8];
    const float* W4   = (const float*)d_in[9];
    const float* b4   = (const float*)d_in[10];
    const float* w5   = (const float*)d_in[11];
    const float* bc5  = (const float*)d_in[12];
    const float* w6   = (const float*)d_in[13];
    const float* bc6  = (const float*)d_in[14];
    const float* Wc1  = (const float*)d_in[15];
    const float* bc1  = (const float*)d_in[16];
    const float* Wc2  = (const float*)d_in[17];
    const float* bc2  = (const float*)d_in[18];
    float* out = (float*)d_out;

    // graph structure
    k_zero_cnt<<<(Nn+255)/256, 256>>>();
    k_build<<<(Ee+255)/256, 256>>>(src, dstp);
    k_dis<<<(Nn+255)/256, 256>>>();

    // weight re-layouts + offset tables (cheap, every launch)
    k_w5t<<<(769*128+255)/256, 256>>>(w5);
    k_w6t<<<(640*256+255)/256, 256>>>(w6);
    k_off6<<<(5808+255)/256, 256>>>();

    // GCN layers: XW (into H) then normalize+aggregate+tanh
    sgemm2<<<dim3(2,792), 256>>>(x, 0, 64, 0, 1,  W1, 0, OF_H, 0, 1, Nn, 256, 64,  nullptr, 0);
    k_agg<<<Nn, 256>>>(OF_X1, b1);
    sgemm2<<<dim3(2,792), 256>>>(nullptr, OF_X1, 256, 0, 1, W2, 0, OF_H, 0, 1, Nn, 256, 256, nullptr, 0);
    k_agg<<<Nn, 256>>>(OF_X2, b2);
    sgemm2<<<dim3(2,792), 256>>>(nullptr, OF_X2, 256, 0, 1, W3, 0, OF_H, 0, 1, Nn, 256, 256, nullptr, 0);
    k_agg<<<Nn, 256>>>(OF_X3, b3);
    k_l4<<<(Nn*32+255)/256, 256>>>(W4);
    k_agg1<<<(Nn+255)/256, 256>>>(b4);

    // sort-pool + gather
    k_topk<<<Gg, 256>>>();
    k_gather<<<Gg*KTOP, 256>>>();

    // conv5 (stride=kernel=769) as GEMM [15840,769]x[769,128] + bias + relu
    // lda=769 (odd) -> scalar A path
    sgemm2<<<dim3(1,124), 256>>>(nullptr, OF_XS, Dd, 0, 0, nullptr, OF_W5T, OF_Y5, 0, 1,
                                 Gg*KTOP, 128, Dd, bc5, 1);
    k_pool<<<(Gg*15*128+255)/256, 256>>>();

    // conv6 as GEMM with row-offset indirection [5808,640]x[640,256], permuted store
    sgemm2<<<dim3(2,46), 256>>>(nullptr, OF_Y2, 0, 1, 1, nullptr, OF_W6T, OF_O6, 1, 11,
                                5808, 256, 640, bc6, 1);

    // dense head
    k_embT<<<(30976+255)/256, 256>>>();
    k_zero_hp<<<(48*256+255)/256, 256>>>();
    k_dense1<<<128, 256>>>(Wc1);
    k_dense2<<<1, 512>>>(bc1, Wc2, bc2, out);
}